// round 3
// baseline (speedup 1.0000x reference)
#include <cuda_runtime.h>
#include <math.h>
#include <stdint.h>

// ---------------------------------------------------------------------------
// Problem constants
// ---------------------------------------------------------------------------
static constexpr int B_   = 128;
static constexpr int C_   = 2048;   // C_ENC
static constexpr int HW   = 49;     // H*W
static constexpr int FIN  = 512;    // F_IN
static constexpr int G_   = 8;      // F_HID
static constexpr int NP   = 192;    // N_PTS (== N_CONVGRID)
static constexpr int S2   = 49;     // (LMAX+1)^2
static constexpr int SO3  = 455;    // sum (2l+1)^2
static constexpr int NG   = 4000;   // N_SO3GRID
static constexpr int GI   = G_ * S2;   // 392
static constexpr int SPLITK = 8;

static constexpr float RS192 = 0.07216878364870323f;  // 1/sqrt(192)
static constexpr float RS512 = 0.04419417382415922f;  // 1/sqrt(512)

// ---------------------------------------------------------------------------
// Scratch (device globals; runtime allocation is forbidden)
// ---------------------------------------------------------------------------
__device__ float d_P[HW * S2];            // 49x49
__device__ float d_q[S2];                 // col sums of P
__device__ float d_psi[FIN * GI];         // [f][g][i]
__device__ float d_bpsi[GI];              // [g][i]
__device__ float d_psi2[G_ * SO3];        // [f][i]
__device__ float d_W2[C_ * GI];           // [c][g*49+i]
__device__ float d_fmapP[(size_t)B_ * C_ * S2];      // 51.4 MB
__device__ float d_x4[B_ * G_ * SO3];     // [b][g][455]
__device__ float d_gact[(size_t)B_ * G_ * NG];       // 16.4 MB
__device__ float d_part[(size_t)SPLITK * B_ * G_ * SO3];
__device__ float d_x5[B_ * G_ * SO3];

__constant__ int c_off2[8] = {0, 1, 10, 35, 84, 165, 286, 455};

// ---------------------------------------------------------------------------
// Small precompute kernels
// ---------------------------------------------------------------------------

// P[hw][i] = (1/sqrt192) * sum_n proj_w[hw][n] * proj_Y[n][i];  q[i] = sum_hw P
__global__ void k_P(const float* __restrict__ proj_w, const float* __restrict__ proj_Y) {
    __shared__ float sP[HW * S2];
    const int tid = threadIdx.x;
    for (int idx = tid; idx < HW * S2; idx += blockDim.x) {
        int hw = idx / S2, i = idx % S2;
        const float* wr = proj_w + hw * NP;
        float acc = 0.f;
        #pragma unroll 4
        for (int n = 0; n < NP; n++) acc += wr[n] * proj_Y[n * S2 + i];
        acc *= RS192;
        sP[idx] = acc;
        d_P[idx] = acc;
    }
    __syncthreads();
    for (int i = tid; i < S2; i += blockDim.x) {
        float acc = 0.f;
        for (int hw = 0; hw < HW; hw++) acc += sP[hw * S2 + i];
        d_q[i] = acc;
    }
}

// psi[f][g][i] = (1/sqrt192) * sum_n fs_w[f][g][n] * fs_Y[n][i]
__global__ void k_psi(const float* __restrict__ fs_w, const float* __restrict__ fs_Y) {
    int t = blockIdx.x * blockDim.x + threadIdx.x;
    if (t >= FIN * GI) return;
    int i = t % S2;
    int fg = t / S2;
    const float* wr = fs_w + (size_t)fg * NP;
    float acc = 0.f;
    #pragma unroll 4
    for (int n = 0; n < NP; n++) acc += wr[n] * fs_Y[n * S2 + i];
    d_psi[t] = acc * RS192;
}

// bpsi[g][i] = (1/sqrt512) * sum_f conv_b[f] * psi[f][g][i]
__global__ void k_bpsi(const float* __restrict__ conv_b) {
    int t = blockIdx.x * blockDim.x + threadIdx.x;
    if (t >= GI) return;
    float acc = 0.f;
    for (int f = 0; f < FIN; f++) acc += conv_b[f] * d_psi[f * GI + t];
    d_bpsi[t] = acc * RS512;
}

// psi2[f][i] = (1/sqrt192) * sum_n so3_w[f][0][n] * so3_D[n][i]
__global__ void k_psi2(const float* __restrict__ so3_w, const float* __restrict__ so3_D) {
    int t = blockIdx.x * blockDim.x + threadIdx.x;
    if (t >= G_ * SO3) return;
    int f = t / SO3, i = t % SO3;
    const float* wr = so3_w + f * NP;
    float acc = 0.f;
    #pragma unroll 4
    for (int n = 0; n < NP; n++) acc += wr[n] * so3_D[n * SO3 + i];
    d_psi2[t] = acc * RS192;
}

// ---------------------------------------------------------------------------
// Generic register-tiled fp32 GEMM:  C = alpha * A @ B
// A: [M,K] row-major (ATRANS=false)  or  [K,M] row-major (ATRANS=true)
// B: [K,N] row-major.  blockIdx.z = split-K slab (writes C + z*M*N).
// ---------------------------------------------------------------------------
template<int BM, int BN, int BK, int TM, int TN, bool ATRANS, bool RELU>
__global__ void sgemm_kernel(const float* __restrict__ A, const float* __restrict__ Bm,
                             float* __restrict__ C, int M, int N, int K,
                             float alpha, int kChunk) {
    constexpr int TX = BN / TN;
    constexpr int TY = BM / TM;
    constexpr int THREADS = TX * TY;
    __shared__ float As[BK][BM];
    __shared__ float Bs[BK][BN];
    const int tid = threadIdx.x;
    const int tx = tid % TX;
    const int ty = tid / TX;
    const int rowBase = blockIdx.y * BM;
    const int colBase = blockIdx.x * BN;
    const int k0 = blockIdx.z * kChunk;
    const int kEnd = min(K, k0 + kChunk);

    float acc[TM][TN];
    #pragma unroll
    for (int i = 0; i < TM; i++)
        #pragma unroll
        for (int j = 0; j < TN; j++) acc[i][j] = 0.f;

    for (int kt = k0; kt < kEnd; kt += BK) {
        if (ATRANS) {
            #pragma unroll
            for (int idx = tid; idx < BK * BM; idx += THREADS) {
                int kk = idx / BM, m = idx % BM;
                int gk = kt + kk, gm = rowBase + m;
                As[kk][m] = (gk < kEnd && gm < M) ? A[(size_t)gk * M + gm] : 0.f;
            }
        } else {
            #pragma unroll
            for (int idx = tid; idx < BM * BK; idx += THREADS) {
                int m = idx / BK, kk = idx % BK;
                int gm = rowBase + m, gk = kt + kk;
                As[kk][m] = (gk < kEnd && gm < M) ? A[(size_t)gm * K + gk] : 0.f;
            }
        }
        #pragma unroll
        for (int idx = tid; idx < BK * BN; idx += THREADS) {
            int kk = idx / BN, n = idx % BN;
            int gk = kt + kk, gn = colBase + n;
            Bs[kk][n] = (gk < kEnd && gn < N) ? Bm[(size_t)gk * N + gn] : 0.f;
        }
        __syncthreads();
        #pragma unroll
        for (int kk = 0; kk < BK; kk++) {
            float a[TM], bb[TN];
            #pragma unroll
            for (int i = 0; i < TM; i++) a[i] = As[kk][ty * TM + i];
            #pragma unroll
            for (int j = 0; j < TN; j++) bb[j] = Bs[kk][tx * TN + j];
            #pragma unroll
            for (int i = 0; i < TM; i++)
                #pragma unroll
                for (int j = 0; j < TN; j++) acc[i][j] += a[i] * bb[j];
        }
        __syncthreads();
    }

    float* Co = C + (size_t)blockIdx.z * M * N;
    #pragma unroll
    for (int i = 0; i < TM; i++) {
        int gm = rowBase + ty * TM + i;
        if (gm >= M) continue;
        #pragma unroll
        for (int j = 0; j < TN; j++) {
            int gn = colBase + tx * TN + j;
            if (gn >= N) continue;
            float v = alpha * acc[i][j];
            if (RELU) v = fmaxf(v, 0.f);
            Co[(size_t)gm * N + gn] = v;
        }
    }
}

// ---------------------------------------------------------------------------
// Stage D: per-l block GEMM.  out[b,g,u,m] = sum_c fmapP[b,c,s+m]*W2[c,g,s+u]
// (W2 already carries 1/sqrt512). grid = (128 b, 7 l), 128 threads.
// Thread computes a 4x4 (u,m) microtile for one g.
// ---------------------------------------------------------------------------
static constexpr int KC = 32;
__global__ void stageD_kernel() {
    const int b = blockIdx.x;
    const int l = blockIdx.y;
    const int d = 2 * l + 1;
    const int s = l * l;
    const int off2 = c_off2[l];
    const int nt = (d + 3) >> 2;        // u/m tiles of 4
    const int tpg = nt * nt;
    const int tid = threadIdx.x;
    const bool active = tid < 8 * tpg;
    int g = 0, ut = 0, mt = 0;
    if (active) { g = tid / tpg; int r = tid % tpg; ut = r / nt; mt = r % nt; }

    __shared__ float Af[KC][16];     // [cc][m]
    __shared__ float Bw[KC][128];    // [cc][g*16+u]

    float acc[4][4];
    #pragma unroll
    for (int i = 0; i < 4; i++)
        #pragma unroll
        for (int j = 0; j < 4; j++) acc[i][j] = 0.f;

    const float* fm = d_fmapP + (size_t)b * C_ * S2;

    for (int c0 = 0; c0 < C_; c0 += KC) {
        #pragma unroll
        for (int idx = tid; idx < KC * 16; idx += 128) {
            int cc = idx >> 4, m = idx & 15;
            Af[cc][m] = (m < d) ? fm[(size_t)(c0 + cc) * S2 + s + m] : 0.f;
        }
        #pragma unroll
        for (int idx = tid; idx < KC * 128; idx += 128) {
            int cc = idx >> 7, r = idx & 127;
            int gg = r >> 4, u = r & 15;
            Bw[cc][r] = (u < d) ? d_W2[(size_t)(c0 + cc) * GI + gg * S2 + s + u] : 0.f;
        }
        __syncthreads();
        if (active) {
            #pragma unroll 8
            for (int cc = 0; cc < KC; cc++) {
                float a[4], bb[4];
                #pragma unroll
                for (int j = 0; j < 4; j++) a[j] = Af[cc][mt * 4 + j];
                #pragma unroll
                for (int i = 0; i < 4; i++) bb[i] = Bw[cc][g * 16 + ut * 4 + i];
                #pragma unroll
                for (int i = 0; i < 4; i++)
                    #pragma unroll
                    for (int j = 0; j < 4; j++) acc[i][j] += bb[i] * a[j];
            }
        }
        __syncthreads();
    }

    if (active) {
        #pragma unroll
        for (int i = 0; i < 4; i++) {
            int u = ut * 4 + i;
            if (u >= d) continue;
            #pragma unroll
            for (int j = 0; j < 4; j++) {
                int m = mt * 4 + j;
                if (m >= d) continue;
                float v = acc[i][j] + d_bpsi[g * S2 + s + u] * d_q[s + m];
                d_x4[(size_t)(b * G_ + g) * SO3 + off2 + u * d + m] = v;
            }
        }
    }
}

// reduce split-K partials:  x5 = sum_z part[z]
__global__ void k_reduce() {
    int t = blockIdx.x * blockDim.x + threadIdx.x;
    const int MN = B_ * G_ * SO3;
    if (t >= MN) return;
    float s = 0.f;
    #pragma unroll
    for (int z = 0; z < SPLITK; z++) s += d_part[(size_t)z * MN + t];
    d_x5[t] = s;
}

// Stage H: so3->so3 conv, F_HID=8 -> 1 channel.
// out[b, off2 + v*d + m] = (1/sqrt(8d)) * sum_{f,u} x5[b,f,off2+u*d+m]*psi2[f,off2+u*d+v]
__global__ void stageH_kernel(float* __restrict__ out) {
    int t = blockIdx.x * blockDim.x + threadIdx.x;
    if (t >= B_ * SO3) return;
    int b = t / SO3, j = t % SO3;
    int l = 6;
    while (j < c_off2[l]) l--;
    int d = 2 * l + 1;
    int r = j - c_off2[l];
    int v = r / d, m = r % d;
    float acc = 0.f;
    #pragma unroll
    for (int f = 0; f < G_; f++) {
        const float* xr = d_x5 + (size_t)(b * G_ + f) * SO3 + c_off2[l];
        const float* pr = d_psi2 + f * SO3 + c_off2[l];
        for (int u = 0; u < d; u++) acc += xr[u * d + m] * pr[u * d + v];
    }
    out[t] = acc * (1.0f / sqrtf(8.0f * d));
}

// ---------------------------------------------------------------------------
// Host launcher
// ---------------------------------------------------------------------------
extern "C" void kernel_launch(void* const* d_in, const int* in_sizes, int n_in,
                              void* d_out, int out_size) {
    const float* fmap     = (const float*)d_in[0];   // [128,2048,7,7]
    const float* conv_w   = (const float*)d_in[1];   // [512,2048]
    const float* conv_b   = (const float*)d_in[2];   // [512]
    const float* proj_w   = (const float*)d_in[3];   // [7,7,192]
    const float* proj_Y   = (const float*)d_in[4];   // [192,49]
    const float* fs_w     = (const float*)d_in[5];   // [512,8,192]
    const float* fs_Y     = (const float*)d_in[6];   // [192,49]
    const float* act_to   = (const float*)d_in[7];   // [455,4000]
    const float* act_from = (const float*)d_in[8];   // [4000,455]
    const float* so3_w    = (const float*)d_in[9];   // [8,1,192]
    const float* so3_D    = (const float*)d_in[10];  // [192,455]
    float* out = (float*)d_out;                      // [128,1,455]

    // symbol addresses (host API, capture-safe: no stream work, no allocs)
    float *pP, *pPsi, *pW2, *pFmapP, *pX4, *pGact, *pPart, *pX5;
    cudaGetSymbolAddress((void**)&pP,     d_P);
    cudaGetSymbolAddress((void**)&pPsi,   d_psi);
    cudaGetSymbolAddress((void**)&pW2,    d_W2);
    cudaGetSymbolAddress((void**)&pFmapP, d_fmapP);
    cudaGetSymbolAddress((void**)&pX4,    d_x4);
    cudaGetSymbolAddress((void**)&pGact,  d_gact);
    cudaGetSymbolAddress((void**)&pPart,  d_part);
    cudaGetSymbolAddress((void**)&pX5,    d_x5);

    // 1) small precomputes
    k_P<<<1, 256>>>(proj_w, proj_Y);
    k_psi<<<(FIN * GI + 255) / 256, 256>>>(fs_w, fs_Y);
    k_bpsi<<<(GI + 255) / 256, 256>>>(conv_b);
    k_psi2<<<(G_ * SO3 + 255) / 256, 256>>>(so3_w, so3_D);

    // 2) W2[c, g*49+i] = (1/sqrt512) conv_w^T @ psi    (M=2048, N=392, K=512)
    sgemm_kernel<64, 64, 8, 4, 4, true, false>
        <<<dim3(7, 32, 1), 256>>>(conv_w, pPsi, pW2, C_, GI, FIN, RS512, FIN);

    // 3) fmapP = fmap(rows=b*c) @ P                    (M=262144, N=49, K=49)
    sgemm_kernel<128, 64, 8, 8, 4, false, false>
        <<<dim3(1, (B_ * C_) / 128, 1), 256>>>(fmap, pP, pFmapP,
                                               B_ * C_, S2, HW, 1.0f, HW);

    // 4) s2->so3 block GEMMs + bias -> x4
    stageD_kernel<<<dim3(B_, 7), 128>>>();

    // 5) g = relu(x4 @ act_to)                          (M=1024, N=4000, K=455)
    sgemm_kernel<128, 128, 8, 8, 8, false, true>
        <<<dim3((NG + 127) / 128, (B_ * G_) / 128, 1), 256>>>(
            pX4, act_to, pGact, B_ * G_, NG, SO3, 1.0f, SO3);

    // 6) x5 = g @ act_from (split-K=8 for SM occupancy) (M=1024, N=455, K=4000)
    sgemm_kernel<128, 128, 8, 8, 8, false, false>
        <<<dim3((SO3 + 127) / 128, (B_ * G_) / 128, SPLITK), 256>>>(
            pGact, act_from, pPart, B_ * G_, SO3, NG, 1.0f, NG / SPLITK);
    k_reduce<<<(B_ * G_ * SO3 + 255) / 256, 256>>>();

    // 7) so3->so3 conv -> output
    stageH_kernel<<<(B_ * SO3 + 255) / 256, 256>>>(out);
}